// round 15
// baseline (speedup 1.0000x reference)
#include <cuda_runtime.h>
#include <cuda_fp16.h>
#include <math.h>
#include <stdint.h>

// Shapes (fixed by the problem)
#define BDIM 1024
#define DDIM 8
#define NSTEPS 100
#define LAGV 10
#define WWIN 11
#define NT (BDIM*WWIN)        // 11264 rows (b*11+w)
#define KIN 4369
#define KPAD 4416             // /64 halves (projection BK=64)
#define HID 512
#define G4 2048               // 4*HID gate width

// ---------------- scratch (device globals; no allocation allowed) ----------
__device__ __align__(16) float g_x[BDIM*(NSTEPS+1)*DDIM];
__device__ __align__(16) float g_suminc[BDIM*WWIN*DDIM];
__device__ __align__(16) float g_payoff[BDIM];
__device__ __align__(16) __half g_txp[(size_t)NT*KPAD];       // fp16 signature rows
__device__ __align__(16) __half g_WihF[(size_t)G4*KPAD];      // gate-permuted fp16
__device__ __align__(16) __half g_WihG[(size_t)G4*KPAD];
__device__ __align__(16) __half g_WhhF[(size_t)G4*HID];
__device__ __align__(16) __half g_WhhG[(size_t)G4*HID];
__device__ __align__(16) float  g_bcF[G4], g_bcG[G4];         // combined bias (fp32)
__device__ __align__(16) __half g_W0F[HID*HID], g_W1F[HID*HID];
__device__ __align__(16) __half g_W0G[HID*HID], g_W1G[HID*HID];
__device__ __align__(16) float  g_preF[(size_t)NT*G4];        // fp32 pre-activations
__device__ __align__(16) float  g_preG[(size_t)NT*G4];
__device__ __align__(16) __half g_hF0[BDIM*HID], g_hF1[BDIM*HID];   // ping-pong h
__device__ __align__(16) __half g_hG0[BDIM*HID], g_hG1[BDIM*HID];
__device__ __align__(16) float  g_cF[BDIM*HID], g_cG[BDIM*HID];
__device__ __align__(16) __half g_hsF[(size_t)NT*HID], g_hsG[(size_t)NT*HID];
__device__ __align__(16) __half g_bufA[(size_t)NT*HID],  g_bufB[(size_t)NT*HID];
__device__ __align__(16) __half g_bufA2[(size_t)NT*HID], g_bufB2[(size_t)NT*HID];
__device__ float g_Y[NT];
__device__ float g_Z[NT*DDIM];

// ---------------- helpers -------------------------------------------------
__device__ __forceinline__ void cpasync16(uint32_t dst, const void* src) {
    asm volatile("cp.async.cg.shared.global [%0], [%1], 16;" :: "r"(dst), "l"(src));
}
__device__ __forceinline__ void cpcommit() {
    asm volatile("cp.async.commit_group;");
}
template<int NPend> __device__ __forceinline__ void cpwait() {
    asm volatile("cp.async.wait_group %0;" :: "n"(NPend));
}
__device__ __forceinline__ void ldm4(uint32_t addr, uint32_t& r0, uint32_t& r1,
                                     uint32_t& r2, uint32_t& r3) {
    asm volatile("ldmatrix.sync.aligned.m8n8.x4.shared.b16 {%0,%1,%2,%3}, [%4];"
                 : "=r"(r0), "=r"(r1), "=r"(r2), "=r"(r3) : "r"(addr));
}
__device__ __forceinline__ void mma16(float& c0, float& c1, float& c2, float& c3,
                                      uint32_t a0, uint32_t a1, uint32_t a2, uint32_t a3,
                                      uint32_t b0, uint32_t b1) {
    asm volatile(
        "mma.sync.aligned.m16n8k16.row.col.f32.f16.f16.f32 "
        "{%0,%1,%2,%3}, {%4,%5,%6,%7}, {%8,%9}, {%0,%1,%2,%3};"
        : "+f"(c0), "+f"(c1), "+f"(c2), "+f"(c3)
        : "r"(a0), "r"(a1), "r"(a2), "r"(a3), "r"(b0), "r"(b1));
}
// fast sigmoid / tanh via MUFU ex2 + fast reciprocal (rel err ~1e-6,
// far inside tolerance; NOT the 2^-11 tanh.approx)
__device__ __forceinline__ float fsigm(float x) {
    return __fdividef(1.f, 1.f + __expf(-x));
}
__device__ __forceinline__ float ftanh(float x) {
    float e = __expf(-2.f * x);
    return __fdividef(1.f - e, 1.f + e);
}

// ---------------- FP16 GEMM core: C[m,n] = sum_k A[m,k]*B[n,k] ------------
// CTA tile 128(M)x256(N), 512 threads, 16 warps (warp tile 32x64).
// Dual BK specialization (round-13/14 finding):
//   BK64=1: BK=64, 4 stages, 221KB — long-K (projections): fewest barriers.
//   BK64=0: BK=32, 5 stages, 154KB — short-K (recurrence/FFN): short ramp.
// Single __syncthreads per ktile; next stage issued RIGHT AFTER the barrier
// (slot (kt-1)%NST is provably drained) for max prefetch flight time.
// MODE 0 = plain epilogue (OUTH half/float), MODE 1 = fused LSTM cell
// (ping-pong h: reads hin, writes hout — NEVER in place; round-7 race fix).
#define TG_SMEM64 221184     // 4 * (128+256)*72*2
#define TG_SMEM32 153600     // 5 * (128+256)*40*2

template<int MODE, int OUTH, int BK64>
__device__ __forceinline__ void tc_body(
    const __half* __restrict__ A, int lda,
    const __half* __restrict__ B, int ldb,
    void* __restrict__ C, int ldc, int K,
    const float* __restrict__ bias, int relu,
    const float* __restrict__ pre,     // MODE 1
    float* __restrict__ cst, __half* __restrict__ hout,
    __half* __restrict__ hs, int t,
    int bm, int bn)
{
    constexpr int  BK    = BK64 ? 64 : 32;
    constexpr uint32_t PITCH = BK64 ? 72u : 40u;     // halves/row, conflict-free
    constexpr uint32_t PB    = PITCH * 2u;           // bytes/row
    constexpr uint32_t AHL   = 128u * PITCH;
    constexpr uint32_t STB   = (128u + 256u) * PITCH * 2u;
    constexpr int  NST   = BK64 ? 4 : 5;
    constexpr int  ACH   = 128*(BK/8)/512;           // A 16B-chunks per thread
    constexpr int  BCH   = 256*(BK/8)/512;           // B 16B-chunks per thread
    constexpr int  CPR   = BK/8;                     // chunks per row

    extern __shared__ float sm[];
    uint32_t smu = (uint32_t)__cvta_generic_to_shared(sm);
    int tid = threadIdx.x, warp = tid >> 5, lane = tid & 31;
    int wm = (warp >> 2) * 32;       // 4 M-slices of 32
    int wn = (warp & 3) * 64;        // 4 N-slices of 64
    int gid = lane >> 2, tig = lane & 3;

    // ldmatrix per-lane selectors (b16, 16B rows = 8 halves)
    int a_row = lane & 15;
    uint32_t akb = (uint32_t)(lane >> 4) * 16u;      // k-half offset bytes
    int b_row = ((lane & 16) >> 1) + (lane & 7);
    uint32_t bkb = (lane & 8) ? 16u : 0u;

    float acc[2][8][4];
    #pragma unroll
    for (int i = 0; i < 2; i++)
        #pragma unroll
        for (int j = 0; j < 8; j++)
            #pragma unroll
            for (int q = 0; q < 4; q++) acc[i][j][q] = 0.f;

    int nk = K / BK;

    auto issue = [&](int kt, int slot) {
        uint32_t base = smu + (uint32_t)slot * STB;
        int k0 = kt * BK;
        #pragma unroll
        for (int j = 0; j < ACH; j++) {
            int idx = tid + j*512;
            int row = idx / CPR, c = idx % CPR;
            cpasync16(base + (uint32_t)row*PB + (uint32_t)c*16u,
                      A + (size_t)(bm + row)*lda + k0 + c*8);
        }
        uint32_t bbase = base + AHL*2u;
        #pragma unroll
        for (int j = 0; j < BCH; j++) {
            int idx = tid + j*512;
            int row = idx / CPR, c = idx % CPR;
            cpasync16(bbase + (uint32_t)row*PB + (uint32_t)c*16u,
                      B + (size_t)(bn + row)*ldb + k0 + c*8);
        }
    };

    #pragma unroll
    for (int p = 0; p < NST-1; p++) { issue(p, p); cpcommit(); }

    for (int kt = 0; kt < nk; kt++) {
        cpwait<NST-2>();                  // stage kt complete
        __syncthreads();

        // issue into slot (kt+NST-1)%NST == (kt-1)%NST: every thread finished
        // reading that slot before this barrier -> safe, and maximal flight
        if (kt + NST-1 < nk) issue(kt + NST-1, (kt + NST-1) % NST);
        cpcommit();                       // uniform group count

        uint32_t aB = smu + (uint32_t)(kt % NST) * STB;
        uint32_t bB = aB + AHL*2u;
        #pragma unroll
        for (int s = 0; s < BK/16; s++) { // k16 steps per ktile
            uint32_t af[2][4], bf[4][4];
            #pragma unroll
            for (int mf = 0; mf < 2; mf++)
                ldm4(aB + (uint32_t)(wm + mf*16 + a_row)*PB + (uint32_t)s*32u + akb,
                     af[mf][0], af[mf][1], af[mf][2], af[mf][3]);
            #pragma unroll
            for (int np = 0; np < 4; np++)
                ldm4(bB + (uint32_t)(wn + np*16 + b_row)*PB + (uint32_t)s*32u + bkb,
                     bf[np][0], bf[np][1], bf[np][2], bf[np][3]);
            #pragma unroll
            for (int mf = 0; mf < 2; mf++)
                #pragma unroll
                for (int nf = 0; nf < 8; nf++) {
                    int np = nf >> 1, hh = (nf & 1) * 2;
                    mma16(acc[mf][nf][0], acc[mf][nf][1], acc[mf][nf][2], acc[mf][nf][3],
                          af[mf][0], af[mf][1], af[mf][2], af[mf][3],
                          bf[np][hh], bf[np][hh+1]);
                }
        }
    }

    if (MODE == 0) {
        #pragma unroll
        for (int mf = 0; mf < 2; mf++) {
            #pragma unroll
            for (int nf = 0; nf < 8; nf++) {
                int r0 = bm + wm + mf*16 + gid;
                int cc = bn + wn + nf*8 + 2*tig;
                float b0v = bias ? bias[cc]   : 0.f;
                float b1v = bias ? bias[cc+1] : 0.f;
                float v0 = acc[mf][nf][0] + b0v;
                float v1 = acc[mf][nf][1] + b1v;
                float v2 = acc[mf][nf][2] + b0v;
                float v3 = acc[mf][nf][3] + b1v;
                if (relu) { v0=fmaxf(v0,0.f); v1=fmaxf(v1,0.f);
                            v2=fmaxf(v2,0.f); v3=fmaxf(v3,0.f); }
                if (OUTH) {
                    __half* Ch = (__half*)C;
                    *(__half2*)&Ch[(size_t)r0*ldc + cc]     = __floats2half2_rn(v0, v1);
                    *(__half2*)&Ch[(size_t)(r0+8)*ldc + cc] = __floats2half2_rn(v2, v3);
                } else {
                    float* Cf = (float*)C;
                    *(float2*)&Cf[(size_t)r0*ldc + cc]     = make_float2(v0, v1);
                    *(float2*)&Cf[(size_t)(r0+8)*ldc + cc] = make_float2(v2, v3);
                }
            }
        }
    } else {
        // fused LSTM cell: cols are gate-interleaved (4u+{i,f,g,o})
        #pragma unroll
        for (int mf = 0; mf < 2; mf++) {
            #pragma unroll
            for (int nf = 0; nf < 8; nf++) {
                int r0 = bm + wm + mf*16 + gid;          // batch index (even-lane row)
                int cc = bn + wn + nf*8 + 2*tig;
                size_t n0 = ((size_t)r0*WWIN + t)*G4;
                size_t n1 = ((size_t)(r0+8)*WWIN + t)*G4;
                float bc0 = bias[cc], bc1 = bias[cc+1];
                float v0 = acc[mf][nf][0] + pre[n0 + cc]     + bc0;
                float v1 = acc[mf][nf][1] + pre[n0 + cc + 1] + bc1;
                float v2 = acc[mf][nf][2] + pre[n1 + cc]     + bc0;
                float v3 = acc[mf][nf][3] + pre[n1 + cc + 1] + bc1;
                int odd = tig & 1;
                float s0 = odd ? v0 : v2;
                float s1 = odd ? v1 : v3;
                float x0 = __shfl_xor_sync(0xffffffffu, s0, 1);
                float x1 = __shfl_xor_sync(0xffffffffu, s1, 1);
                float gi = odd ? x0 : v0;
                float gf = odd ? x1 : v1;
                float gg = odd ? v2 : x0;
                float go = odd ? v3 : x1;
                int brow = r0 + (odd ? 8 : 0);
                int u = ((bn + wn + nf*8) >> 2) + (tig >> 1);
                int idx = brow*HID + u;
                float cv = cst[idx];
                cv = fsigm(gf)*cv + fsigm(gi)*ftanh(gg);
                float hv = fsigm(go)*ftanh(cv);
                cst[idx] = cv;
                __half hvh = __float2half(hv);
                hout[idx] = hvh;
                hs[((size_t)brow*WWIN + t)*HID + u] = hvh;
            }
        }
    }
}

// projections: BK=64, dual-net via z
__global__ void __launch_bounds__(512, 1) tc_proj2(
    const __half* __restrict__ A0, const __half* __restrict__ B0,
    float* __restrict__ C0,
    const __half* __restrict__ A1, const __half* __restrict__ B1,
    float* __restrict__ C1,
    int lda, int ldb, int ldc, int K)
{
    int z = blockIdx.z;
    tc_body<0,0,1>(z ? A1 : A0, lda, z ? B1 : B0, ldb,
                   z ? (void*)C1 : (void*)C0, ldc, K, nullptr, 0,
                   nullptr, nullptr, nullptr, nullptr, 0,
                   blockIdx.y*128, blockIdx.x*256);
}

// FFN: BK=32, half output, dual-net via z
__global__ void __launch_bounds__(512, 1) tc_ffn2(
    const __half* __restrict__ A0, const __half* __restrict__ B0,
    __half* __restrict__ C0, const float* __restrict__ bias0,
    const __half* __restrict__ A1, const __half* __restrict__ B1,
    __half* __restrict__ C1, const float* __restrict__ bias1,
    int lda, int ldb, int ldc, int K, int relu)
{
    int z = blockIdx.z;
    tc_body<0,1,0>(z ? A1 : A0, lda, z ? B1 : B0, ldb,
                   z ? (void*)C1 : (void*)C0, ldc, K,
                   z ? bias1 : bias0, relu,
                   nullptr, nullptr, nullptr, nullptr, 0,
                   blockIdx.y*128, blockIdx.x*256);
}

// recurrence: BK=32, fused LSTM cell, ping-pong h (never in place)
__global__ void __launch_bounds__(512, 1) tc_cell(
    const __half* __restrict__ hinF, __half* __restrict__ houtF,
    const __half* __restrict__ hinG, __half* __restrict__ houtG, int t)
{
    int z = blockIdx.z;
    tc_body<1,0,0>(z ? hinG : hinF, HID, z ? g_WhhG : g_WhhF, HID,
                   nullptr, 0, HID, z ? g_bcG : g_bcF, 0,
                   z ? g_preG : g_preF,
                   z ? g_cG : g_cF, z ? houtG : houtF, z ? g_hsG : g_hsF, t,
                   blockIdx.y*128, blockIdx.x*256);
}

// ---------------- merged preprocessing (one launch) ------------------------
// permuted row p <- orig row (p&3)*512 + (p>>2)
__global__ void k_prep(const float* __restrict__ fWih, const float* __restrict__ gWih,
                       const float* __restrict__ fWhh, const float* __restrict__ gWhh,
                       const float* __restrict__ fbi,  const float* __restrict__ fbh,
                       const float* __restrict__ gbi,  const float* __restrict__ gbh,
                       const float* __restrict__ fW0,  const float* __restrict__ fW1,
                       const float* __restrict__ gW0,  const float* __restrict__ gW1) {
    int i = blockIdx.x*blockDim.x + threadIdx.x;
    if (i < G4*KPAD) {
        int r = i / KPAD, c = i - r*KPAD;
        int ro = (r & 3)*512 + (r >> 2);
        float vf = 0.f, vg = 0.f;
        if (c < KIN) { vf = fWih[(size_t)ro*KIN + c]; vg = gWih[(size_t)ro*KIN + c]; }
        g_WihF[i] = __float2half(vf); g_WihG[i] = __float2half(vg);
    }
    if (i < G4*HID) {
        int r = i / HID, c = i - r*HID;
        int ro = (r & 3)*512 + (r >> 2);
        g_WhhF[i] = __float2half(fWhh[(size_t)ro*HID + c]);
        g_WhhG[i] = __float2half(gWhh[(size_t)ro*HID + c]);
    }
    if (i < G4) {
        int o = (i & 3)*512 + (i >> 2);
        g_bcF[i] = fbi[o] + fbh[o];
        g_bcG[i] = gbi[o] + gbh[o];
    }
    if (i < HID*HID) {
        g_W0F[i] = __float2half(fW0[i]); g_W1F[i] = __float2half(fW1[i]);
        g_W0G[i] = __float2half(gW0[i]); g_W1G[i] = __float2half(gW1[i]);
    }
    if (i < BDIM*HID) {
        g_hF0[i] = __float2half(0.f); g_hG0[i] = __float2half(0.f);
        g_cF[i] = 0.f; g_cG[i] = 0.f;
    }
}

// ---------------- SDE paths + sum_inc + payoff ----------------------------
__global__ void k_paths(const float* __restrict__ ts, const float* __restrict__ x0,
                        const float* __restrict__ noise) {
    int gid = blockIdx.x*blockDim.x + threadIdx.x;
    if (gid >= BDIM*DDIM) return;
    int b = gid >> 3, k = gid & 7;
    float x = x0[b*8 + k];
    g_x[(size_t)(b*101)*8 + k] = x;
    float si = 0.f;
    float bk = x;
    #pragma unroll
    for (int s = 1; s < 8; s <<= 1) bk += __shfl_xor_sync(0xffffffffu, bk, s);
    bk *= 0.125f;
    float bmax = bk, blast = bk;
    for (int t = 0; t < NSTEPS; t++) {
        float h  = ts[t+1] - ts[t];
        float dw = noise[((size_t)b*NSTEPS + t)*8 + k] * sqrtf(h);
        x = x + 0.05f*x*h + 0.2f*x*dw;
        g_x[(size_t)(b*101 + t + 1)*8 + k] = x;
        si += dw;
        if ((t % LAGV) == (LAGV-1)) {
            g_suminc[(size_t)(b*WWIN + t/LAGV)*8 + k] = si;
            si = 0.f;
        }
        float bb = x;
        #pragma unroll
        for (int s = 1; s < 8; s <<= 1) bb += __shfl_xor_sync(0xffffffffu, bb, s);
        bb *= 0.125f;
        bmax = fmaxf(bmax, bb);
        blast = bb;
    }
    g_suminc[(size_t)(b*WWIN + 10)*8 + k] = 0.f;
    if (k == 0) g_payoff[b] = bmax - blast;
}

// ---------------- lead-lag signature (depth 3, c=16) ----------------------
__global__ void __launch_bounds__(256) k_sig(const float* __restrict__ ts) {
    __shared__ float S1[16];
    __shared__ float S2[256];
    __shared__ float S3[4096];
    __shared__ float dl[10][8];
    int n = blockIdx.x;
    int b = n / WWIN, w = n - b*WWIN;
    int tid = threadIdx.x;

    if (tid < 80) {
        int i = tid >> 3, k = tid & 7;
        float v;
        if (w == 0) {
            v = (i == 0) ? g_x[(size_t)(b*101)*8 + k] : 0.f;
        } else {
            int base = (w-1)*LAGV + i;
            v = g_x[(size_t)(b*101 + base + 1)*8 + k] - g_x[(size_t)(b*101 + base)*8 + k];
        }
        dl[i][k] = v;
    }
    for (int j = tid; j < 4096; j += 256) S3[j] = 0.f;
    S2[tid] = 0.f;
    if (tid < 16) S1[tid] = 0.f;
    __syncthreads();

    int ni = (w == 0) ? 1 : 10;
    int a = tid >> 4, bbx = tid & 15;
    for (int i = 0; i < ni; i++) {
        #pragma unroll
        for (int ph = 0; ph < 2; ph++) {
            int o = ph ? 0 : 8;
            float s2ab = S2[tid];
            float s1a  = S1[a];
            float db = (bbx >= o && bbx < o+8) ? dl[i][bbx - o] : 0.f;
            float da = (a   >= o && a   < o+8) ? dl[i][a   - o] : 0.f;
            float coef = s2ab + db*(0.5f*s1a + (1.f/6.f)*da);
            float* s3p = &S3[(tid << 4) + o];
            #pragma unroll
            for (int c = 0; c < 8; c++) s3p[c] += coef * dl[i][c];
            __syncthreads();
            if (tid < 128) {
                int aa = tid >> 3, bi = tid & 7;
                float daa = (aa >= o && aa < o+8) ? dl[i][aa - o] : 0.f;
                S2[aa*16 + o + bi] += (S1[aa] + 0.5f*daa) * dl[i][bi];
            }
            __syncthreads();
            if (tid < 8) S1[o + tid] += dl[i][tid];
            __syncthreads();
        }
    }

    float tc = ts[w * LAGV];
    __half* row = &g_txp[(size_t)n * KPAD];
    for (int j = tid; j < KPAD; j += 256) {
        float v;
        if      (j == 0)   v = tc;
        else if (j < 17)   v = S1[j - 1];
        else if (j < 273)  v = S2[j - 17];
        else if (j < KIN)  v = S3[j - 273];
        else               v = 0.f;
        row[j] = __float2half(v);
    }
}

// ---------------- merged skinny output heads (Y + Z, one launch) -----------
__global__ void k_outYZ(const __half* __restrict__ bufY, const float* __restrict__ W2y,
                        const float* __restrict__ b2y,
                        const __half* __restrict__ bufZ, const float* __restrict__ W2z,
                        const float* __restrict__ b2z) {
    int n = blockIdx.x;
    int wrp = threadIdx.x >> 5, lane = threadIdx.x & 31;
    if (wrp < 8) {
        const __half* row = bufZ + (size_t)n*HID;
        const float* wr = W2z + (size_t)wrp*HID;
        float s = 0.f;
        #pragma unroll
        for (int k = lane; k < HID; k += 32) s += __half2float(row[k])*wr[k];
        #pragma unroll
        for (int o = 16; o; o >>= 1) s += __shfl_xor_sync(0xffffffffu, s, o);
        if (lane == 0) g_Z[n*DDIM + wrp] = s + b2z[wrp];
    } else {
        const __half* row = bufY + (size_t)n*HID;
        float s = 0.f;
        #pragma unroll
        for (int k = lane; k < HID; k += 32) s += __half2float(row[k])*W2y[k];
        #pragma unroll
        for (int o = 16; o; o >>= 1) s += __shfl_xor_sync(0xffffffffu, s, o);
        if (lane == 0) g_Y[n] = s + b2y[0];
    }
}

// ---------------- loss + output assembly (deterministic, one block) ------
__global__ void k_loss(const float* __restrict__ ts, float* __restrict__ out) {
    __shared__ float red[1024];
    int b = threadIdx.x;
    float acc = 0.f;
    #pragma unroll 1
    for (int w = 0; w < WWIN; w++) {
        int n = b*WWIN + w;
        float y = g_Y[n];
        float pr = y;
        #pragma unroll
        for (int k = 0; k < DDIM; k++)
            pr += g_Z[n*DDIM + k]*g_suminc[(size_t)n*DDIM + k];
        float tg;
        if (w < WWIN-1) {
            float disc = expf(-0.05f*(ts[w + LAGV] - ts[w*LAGV]));
            tg = disc * g_Y[n + 1];
        } else {
            tg = g_payoff[b];
        }
        float df = pr - tg;
        acc += df*df;
        out[1 + n] = y;
    }
    out[1 + NT + b] = g_payoff[b];
    red[b] = acc;
    __syncthreads();
    for (int s = 512; s > 0; s >>= 1) {
        if (b < s) red[b] += red[b + s];
        __syncthreads();
    }
    if (b == 0) out[0] = red[0] * (1.f/(float)BDIM);
}

// ---------------- host ----------------------------------------------------
extern "C" void kernel_launch(void* const* d_in, const int* in_sizes, int n_in,
                              void* d_out, int out_size) {
    const float* ts    = (const float*)d_in[0];
    const float* x0    = (const float*)d_in[1];
    const float* noise = (const float*)d_in[2];
    const float* fWih = (const float*)d_in[4];
    const float* fWhh = (const float*)d_in[5];
    const float* fbih = (const float*)d_in[6];
    const float* fbhh = (const float*)d_in[7];
    const float* fW0  = (const float*)d_in[8];
    const float* fb0  = (const float*)d_in[9];
    const float* fW1  = (const float*)d_in[10];
    const float* fb1  = (const float*)d_in[11];
    const float* fW2  = (const float*)d_in[12];
    const float* fb2  = (const float*)d_in[13];
    const float* gWih = (const float*)d_in[14];
    const float* gWhh = (const float*)d_in[15];
    const float* gbih = (const float*)d_in[16];
    const float* gbhh = (const float*)d_in[17];
    const float* gW0  = (const float*)d_in[18];
    const float* gb0  = (const float*)d_in[19];
    const float* gW1  = (const float*)d_in[20];
    const float* gb1  = (const float*)d_in[21];
    const float* gW2  = (const float*)d_in[22];
    const float* gb2  = (const float*)d_in[23];
    float* out = (float*)d_out;

    cudaFuncSetAttribute(tc_proj2, cudaFuncAttributeMaxDynamicSharedMemorySize, TG_SMEM64);
    cudaFuncSetAttribute(tc_ffn2,  cudaFuncAttributeMaxDynamicSharedMemorySize, TG_SMEM32);
    cudaFuncSetAttribute(tc_cell,  cudaFuncAttributeMaxDynamicSharedMemorySize, TG_SMEM32);

    __half *p_txp,*p_WihF,*p_WihG,*p_hsF,*p_hsG;
    __half *p_bufA,*p_bufB,*p_bufA2,*p_bufB2;
    __half *p_W0F,*p_W1F,*p_W0G,*p_W1G;
    __half *p_hF0,*p_hF1,*p_hG0,*p_hG1;
    float *p_preF,*p_preG;
    cudaGetSymbolAddress((void**)&p_txp,  g_txp);
    cudaGetSymbolAddress((void**)&p_WihF, g_WihF);
    cudaGetSymbolAddress((void**)&p_WihG, g_WihG);
    cudaGetSymbolAddress((void**)&p_preF, g_preF);
    cudaGetSymbolAddress((void**)&p_preG, g_preG);
    cudaGetSymbolAddress((void**)&p_hsF,  g_hsF);
    cudaGetSymbolAddress((void**)&p_hsG,  g_hsG);
    cudaGetSymbolAddress((void**)&p_bufA, g_bufA);
    cudaGetSymbolAddress((void**)&p_bufB, g_bufB);
    cudaGetSymbolAddress((void**)&p_bufA2, g_bufA2);
    cudaGetSymbolAddress((void**)&p_bufB2, g_bufB2);
    cudaGetSymbolAddress((void**)&p_W0F,  g_W0F);
    cudaGetSymbolAddress((void**)&p_W1F,  g_W1F);
    cudaGetSymbolAddress((void**)&p_W0G,  g_W0G);
    cudaGetSymbolAddress((void**)&p_W1G,  g_W1G);
    cudaGetSymbolAddress((void**)&p_hF0,  g_hF0);
    cudaGetSymbolAddress((void**)&p_hF1,  g_hF1);
    cudaGetSymbolAddress((void**)&p_hG0,  g_hG0);
    cudaGetSymbolAddress((void**)&p_hG1,  g_hG1);

    k_prep <<<(G4*KPAD + 255)/256, 256>>>(fWih, gWih, fWhh, gWhh,
                                          fbih, fbhh, gbih, gbhh,
                                          fW0, fW1, gW0, gW1);
    k_paths<<<(BDIM*DDIM + 255)/256, 256>>>(ts, x0, noise);
    k_sig  <<<NT, 256>>>(ts);

    // input projections: BK=64 (long K), both nets fused
    dim3 g1(G4/256, NT/128, 2);
    tc_proj2<<<g1, 512, TG_SMEM64>>>(p_txp, p_WihF, p_preF,
                                     p_txp, p_WihG, p_preG,
                                     KPAD, KPAD, G4, KPAD);

    // recurrence: BK=32 (short K), 11 per-step launches, 128-M tile,
    // fused LSTM cell (fast sigmoid/tanh), h ping-ponged (race fix — keep!).
    __half* hF[2] = { p_hF0, p_hF1 };
    __half* hG[2] = { p_hG0, p_hG1 };
    dim3 g2(G4/256, BDIM/128, 2);
    for (int t = 0; t < WWIN; t++)
        tc_cell<<<g2, 512, TG_SMEM32>>>(hF[t & 1], hF[(t + 1) & 1],
                                        hG[t & 1], hG[(t + 1) & 1], t);

    // FFN heads: BK=32 (short K), both nets fused per layer
    dim3 g3(HID/256, NT/128, 2);
    tc_ffn2<<<g3, 512, TG_SMEM32>>>(p_hsF,  p_W0F, p_bufA,  fb0,
                                    p_hsG,  p_W0G, p_bufA2, gb0,
                                    HID, HID, HID, HID, 1);
    tc_ffn2<<<g3, 512, TG_SMEM32>>>(p_bufA,  p_W1F, p_bufB,  fb1,
                                    p_bufA2, p_W1G, p_bufB2, gb1,
                                    HID, HID, HID, HID, 1);
    k_outYZ<<<NT, 288>>>(p_bufB, fW2, fb2, p_bufB2, gW2, gb2);

    // loss + output: [loss(1), Y(11264), payoff(1024)]
    k_loss<<<1, 1024>>>(ts, out);
}

// round 16
// speedup vs baseline: 1.0209x; 1.0209x over previous
#include <cuda_runtime.h>
#include <cuda_fp16.h>
#include <math.h>
#include <stdint.h>

// Shapes (fixed by the problem)
#define BDIM 1024
#define DDIM 8
#define NSTEPS 100
#define LAGV 10
#define WWIN 11
#define NT (BDIM*WWIN)        // 11264 rows (b*11+w)
#define KIN 4369
#define KPAD 4416             // /64 halves (projection BK=64)
#define HID 512
#define G4 2048               // 4*HID gate width

// ---------------- scratch (device globals; no allocation allowed) ----------
__device__ __align__(16) float g_x[BDIM*(NSTEPS+1)*DDIM];
__device__ __align__(16) float g_suminc[BDIM*WWIN*DDIM];
__device__ __align__(16) float g_payoff[BDIM];
__device__ __align__(16) __half g_txp[(size_t)NT*KPAD];       // fp16 signature rows
__device__ __align__(16) __half g_WihF[(size_t)G4*KPAD];      // gate-permuted fp16
__device__ __align__(16) __half g_WihG[(size_t)G4*KPAD];
__device__ __align__(16) __half g_WhhF[(size_t)G4*HID];
__device__ __align__(16) __half g_WhhG[(size_t)G4*HID];
__device__ __align__(16) float  g_bcF[G4], g_bcG[G4];         // combined bias (fp32)
__device__ __align__(16) __half g_W0F[HID*HID], g_W1F[HID*HID];
__device__ __align__(16) __half g_W0G[HID*HID], g_W1G[HID*HID];
__device__ __align__(16) float  g_preF[(size_t)NT*G4];        // fp32 pre-activations
__device__ __align__(16) float  g_preG[(size_t)NT*G4];
__device__ __align__(16) __half g_hF0[BDIM*HID], g_hF1[BDIM*HID];   // ping-pong h
__device__ __align__(16) __half g_hG0[BDIM*HID], g_hG1[BDIM*HID];
__device__ __align__(16) float  g_cF[BDIM*HID], g_cG[BDIM*HID];
__device__ __align__(16) __half g_hsF[(size_t)NT*HID], g_hsG[(size_t)NT*HID];
__device__ __align__(16) __half g_bufA[(size_t)NT*HID],  g_bufB[(size_t)NT*HID];
__device__ __align__(16) __half g_bufA2[(size_t)NT*HID], g_bufB2[(size_t)NT*HID];
__device__ float g_Y[NT];
__device__ float g_Z[NT*DDIM];

// ---------------- helpers -------------------------------------------------
__device__ __forceinline__ void cpasync16(uint32_t dst, const void* src) {
    asm volatile("cp.async.cg.shared.global [%0], [%1], 16;" :: "r"(dst), "l"(src));
}
__device__ __forceinline__ void cpcommit() {
    asm volatile("cp.async.commit_group;");
}
template<int NPend> __device__ __forceinline__ void cpwait() {
    asm volatile("cp.async.wait_group %0;" :: "n"(NPend));
}
__device__ __forceinline__ void ldm4(uint32_t addr, uint32_t& r0, uint32_t& r1,
                                     uint32_t& r2, uint32_t& r3) {
    asm volatile("ldmatrix.sync.aligned.m8n8.x4.shared.b16 {%0,%1,%2,%3}, [%4];"
                 : "=r"(r0), "=r"(r1), "=r"(r2), "=r"(r3) : "r"(addr));
}
__device__ __forceinline__ void mma16(float& c0, float& c1, float& c2, float& c3,
                                      uint32_t a0, uint32_t a1, uint32_t a2, uint32_t a3,
                                      uint32_t b0, uint32_t b1) {
    asm volatile(
        "mma.sync.aligned.m16n8k16.row.col.f32.f16.f16.f32 "
        "{%0,%1,%2,%3}, {%4,%5,%6,%7}, {%8,%9}, {%0,%1,%2,%3};"
        : "+f"(c0), "+f"(c1), "+f"(c2), "+f"(c3)
        : "r"(a0), "r"(a1), "r"(a2), "r"(a3), "r"(b0), "r"(b1));
}
// fast sigmoid / tanh via MUFU ex2 + fast reciprocal (rel err ~1e-6)
__device__ __forceinline__ float fsigm(float x) {
    return __fdividef(1.f, 1.f + __expf(-x));
}
__device__ __forceinline__ float ftanh(float x) {
    float e = __expf(-2.f * x);
    return __fdividef(1.f - e, 1.f + e);
}

// ---------------- FP16 GEMM core: C[m,n] = sum_k A[m,k]*B[n,k] ------------
// CTA tile 128(M)x256(N), 512 threads, 16 warps (warp tile 32x64).
// Dual BK specialization (round-13/14 finding):
//   BK64=1: BK=64, 4 stages, 221KB — long-K (projections): fewest barriers.
//   BK64=0: BK=32, 5 stages, 154KB — short-K (recurrence/FFN): short ramp.
// Single __syncthreads per ktile; next stage issued AFTER the MMA block
// (round-15 finding: issuing before MMAs bloats live regs and stalls HMMA).
// MODE 0 = plain epilogue (OUTH half/float), MODE 1 = fused LSTM cell
// (ping-pong h: reads hin, writes hout — NEVER in place; round-7 race fix).
#define TG_SMEM64 221184     // 4 * (128+256)*72*2
#define TG_SMEM32 153600     // 5 * (128+256)*40*2

template<int MODE, int OUTH, int BK64>
__device__ __forceinline__ void tc_body(
    const __half* __restrict__ A, int lda,
    const __half* __restrict__ B, int ldb,
    void* __restrict__ C, int ldc, int K,
    const float* __restrict__ bias, int relu,
    const float* __restrict__ pre,     // MODE 1
    float* __restrict__ cst, __half* __restrict__ hout,
    __half* __restrict__ hs, int t,
    int bm, int bn)
{
    constexpr int  BK    = BK64 ? 64 : 32;
    constexpr uint32_t PITCH = BK64 ? 72u : 40u;     // halves/row, conflict-free
    constexpr uint32_t PB    = PITCH * 2u;           // bytes/row
    constexpr uint32_t AHL   = 128u * PITCH;
    constexpr uint32_t STB   = (128u + 256u) * PITCH * 2u;
    constexpr int  NST   = BK64 ? 4 : 5;
    constexpr int  ACH   = 128*(BK/8)/512;           // A 16B-chunks per thread
    constexpr int  BCH   = 256*(BK/8)/512;           // B 16B-chunks per thread
    constexpr int  CPR   = BK/8;                     // chunks per row

    extern __shared__ float sm[];
    uint32_t smu = (uint32_t)__cvta_generic_to_shared(sm);
    int tid = threadIdx.x, warp = tid >> 5, lane = tid & 31;
    int wm = (warp >> 2) * 32;       // 4 M-slices of 32
    int wn = (warp & 3) * 64;        // 4 N-slices of 64
    int gid = lane >> 2, tig = lane & 3;

    // ldmatrix per-lane selectors (b16, 16B rows = 8 halves)
    int a_row = lane & 15;
    uint32_t akb = (uint32_t)(lane >> 4) * 16u;      // k-half offset bytes
    int b_row = ((lane & 16) >> 1) + (lane & 7);
    uint32_t bkb = (lane & 8) ? 16u : 0u;

    float acc[2][8][4];
    #pragma unroll
    for (int i = 0; i < 2; i++)
        #pragma unroll
        for (int j = 0; j < 8; j++)
            #pragma unroll
            for (int q = 0; q < 4; q++) acc[i][j][q] = 0.f;

    int nk = K / BK;

    auto issue = [&](int kt, int slot) {
        uint32_t base = smu + (uint32_t)slot * STB;
        int k0 = kt * BK;
        #pragma unroll
        for (int j = 0; j < ACH; j++) {
            int idx = tid + j*512;
            int row = idx / CPR, c = idx % CPR;
            cpasync16(base + (uint32_t)row*PB + (uint32_t)c*16u,
                      A + (size_t)(bm + row)*lda + k0 + c*8);
        }
        uint32_t bbase = base + AHL*2u;
        #pragma unroll
        for (int j = 0; j < BCH; j++) {
            int idx = tid + j*512;
            int row = idx / CPR, c = idx % CPR;
            cpasync16(bbase + (uint32_t)row*PB + (uint32_t)c*16u,
                      B + (size_t)(bn + row)*ldb + k0 + c*8);
        }
    };

    #pragma unroll
    for (int p = 0; p < NST-1; p++) { issue(p, p); cpcommit(); }

    for (int kt = 0; kt < nk; kt++) {
        cpwait<NST-2>();                  // stage kt complete
        __syncthreads();

        uint32_t aB = smu + (uint32_t)(kt % NST) * STB;
        uint32_t bB = aB + AHL*2u;
        #pragma unroll
        for (int s = 0; s < BK/16; s++) { // k16 steps per ktile
            uint32_t af[2][4], bf[4][4];
            #pragma unroll
            for (int mf = 0; mf < 2; mf++)
                ldm4(aB + (uint32_t)(wm + mf*16 + a_row)*PB + (uint32_t)s*32u + akb,
                     af[mf][0], af[mf][1], af[mf][2], af[mf][3]);
            #pragma unroll
            for (int np = 0; np < 4; np++)
                ldm4(bB + (uint32_t)(wn + np*16 + b_row)*PB + (uint32_t)s*32u + bkb,
                     bf[np][0], bf[np][1], bf[np][2], bf[np][3]);
            #pragma unroll
            for (int mf = 0; mf < 2; mf++)
                #pragma unroll
                for (int nf = 0; nf < 8; nf++) {
                    int np = nf >> 1, hh = (nf & 1) * 2;
                    mma16(acc[mf][nf][0], acc[mf][nf][1], acc[mf][nf][2], acc[mf][nf][3],
                          af[mf][0], af[mf][1], af[mf][2], af[mf][3],
                          bf[np][hh], bf[np][hh+1]);
                }
        }
        // issue into slot (kt+NST-1)%NST == (kt-1)%NST: free after barrier
        if (kt + NST-1 < nk) issue(kt + NST-1, (kt + NST-1) % NST);
        cpcommit();                       // uniform group count
    }

    if (MODE == 0) {
        #pragma unroll
        for (int mf = 0; mf < 2; mf++) {
            #pragma unroll
            for (int nf = 0; nf < 8; nf++) {
                int r0 = bm + wm + mf*16 + gid;
                int cc = bn + wn + nf*8 + 2*tig;
                float b0v = bias ? bias[cc]   : 0.f;
                float b1v = bias ? bias[cc+1] : 0.f;
                float v0 = acc[mf][nf][0] + b0v;
                float v1 = acc[mf][nf][1] + b1v;
                float v2 = acc[mf][nf][2] + b0v;
                float v3 = acc[mf][nf][3] + b1v;
                if (relu) { v0=fmaxf(v0,0.f); v1=fmaxf(v1,0.f);
                            v2=fmaxf(v2,0.f); v3=fmaxf(v3,0.f); }
                if (OUTH) {
                    __half* Ch = (__half*)C;
                    *(__half2*)&Ch[(size_t)r0*ldc + cc]     = __floats2half2_rn(v0, v1);
                    *(__half2*)&Ch[(size_t)(r0+8)*ldc + cc] = __floats2half2_rn(v2, v3);
                } else {
                    float* Cf = (float*)C;
                    *(float2*)&Cf[(size_t)r0*ldc + cc]     = make_float2(v0, v1);
                    *(float2*)&Cf[(size_t)(r0+8)*ldc + cc] = make_float2(v2, v3);
                }
            }
        }
    } else {
        // fused LSTM cell: cols are gate-interleaved (4u+{i,f,g,o})
        #pragma unroll
        for (int mf = 0; mf < 2; mf++) {
            #pragma unroll
            for (int nf = 0; nf < 8; nf++) {
                int r0 = bm + wm + mf*16 + gid;          // batch index (even-lane row)
                int cc = bn + wn + nf*8 + 2*tig;
                size_t n0 = ((size_t)r0*WWIN + t)*G4;
                size_t n1 = ((size_t)(r0+8)*WWIN + t)*G4;
                float bc0 = bias[cc], bc1 = bias[cc+1];
                float v0 = acc[mf][nf][0] + pre[n0 + cc]     + bc0;
                float v1 = acc[mf][nf][1] + pre[n0 + cc + 1] + bc1;
                float v2 = acc[mf][nf][2] + pre[n1 + cc]     + bc0;
                float v3 = acc[mf][nf][3] + pre[n1 + cc + 1] + bc1;
                int odd = tig & 1;
                float s0 = odd ? v0 : v2;
                float s1 = odd ? v1 : v3;
                float x0 = __shfl_xor_sync(0xffffffffu, s0, 1);
                float x1 = __shfl_xor_sync(0xffffffffu, s1, 1);
                float gi = odd ? x0 : v0;
                float gf = odd ? x1 : v1;
                float gg = odd ? v2 : x0;
                float go = odd ? v3 : x1;
                int brow = r0 + (odd ? 8 : 0);
                int u = ((bn + wn + nf*8) >> 2) + (tig >> 1);
                int idx = brow*HID + u;
                float cv = cst[idx];
                cv = fsigm(gf)*cv + fsigm(gi)*ftanh(gg);
                float hv = fsigm(go)*ftanh(cv);
                cst[idx] = cv;
                __half hvh = __float2half(hv);
                hout[idx] = hvh;
                hs[((size_t)brow*WWIN + t)*HID + u] = hvh;
            }
        }
    }
}

// projections: BK=64, dual-net via z
__global__ void __launch_bounds__(512, 1) tc_proj2(
    const __half* __restrict__ A0, const __half* __restrict__ B0,
    float* __restrict__ C0,
    const __half* __restrict__ A1, const __half* __restrict__ B1,
    float* __restrict__ C1,
    int lda, int ldb, int ldc, int K)
{
    int z = blockIdx.z;
    tc_body<0,0,1>(z ? A1 : A0, lda, z ? B1 : B0, ldb,
                   z ? (void*)C1 : (void*)C0, ldc, K, nullptr, 0,
                   nullptr, nullptr, nullptr, nullptr, 0,
                   blockIdx.y*128, blockIdx.x*256);
}

// FFN: BK=32, half output, dual-net via z
__global__ void __launch_bounds__(512, 1) tc_ffn2(
    const __half* __restrict__ A0, const __half* __restrict__ B0,
    __half* __restrict__ C0, const float* __restrict__ bias0,
    const __half* __restrict__ A1, const __half* __restrict__ B1,
    __half* __restrict__ C1, const float* __restrict__ bias1,
    int lda, int ldb, int ldc, int K, int relu)
{
    int z = blockIdx.z;
    tc_body<0,1,0>(z ? A1 : A0, lda, z ? B1 : B0, ldb,
                   z ? (void*)C1 : (void*)C0, ldc, K,
                   z ? bias1 : bias0, relu,
                   nullptr, nullptr, nullptr, nullptr, 0,
                   blockIdx.y*128, blockIdx.x*256);
}

// recurrence: BK=32, fused LSTM cell, ping-pong h (never in place)
__global__ void __launch_bounds__(512, 1) tc_cell(
    const __half* __restrict__ hinF, __half* __restrict__ houtF,
    const __half* __restrict__ hinG, __half* __restrict__ houtG, int t)
{
    int z = blockIdx.z;
    tc_body<1,0,0>(z ? hinG : hinF, HID, z ? g_WhhG : g_WhhF, HID,
                   nullptr, 0, HID, z ? g_bcG : g_bcF, 0,
                   z ? g_preG : g_preF,
                   z ? g_cG : g_cF, z ? houtG : houtF, z ? g_hsG : g_hsF, t,
                   blockIdx.y*128, blockIdx.x*256);
}

// ---------------- merged preprocessing (one launch) ------------------------
// permuted row p <- orig row (p&3)*512 + (p>>2)
__global__ void k_prep(const float* __restrict__ fWih, const float* __restrict__ gWih,
                       const float* __restrict__ fWhh, const float* __restrict__ gWhh,
                       const float* __restrict__ fbi,  const float* __restrict__ fbh,
                       const float* __restrict__ gbi,  const float* __restrict__ gbh,
                       const float* __restrict__ fW0,  const float* __restrict__ fW1,
                       const float* __restrict__ gW0,  const float* __restrict__ gW1) {
    int i = blockIdx.x*blockDim.x + threadIdx.x;
    if (i < G4*KPAD) {
        int r = i / KPAD, c = i - r*KPAD;
        int ro = (r & 3)*512 + (r >> 2);
        float vf = 0.f, vg = 0.f;
        if (c < KIN) { vf = fWih[(size_t)ro*KIN + c]; vg = gWih[(size_t)ro*KIN + c]; }
        g_WihF[i] = __float2half(vf); g_WihG[i] = __float2half(vg);
    }
    if (i < G4*HID) {
        int r = i / HID, c = i - r*HID;
        int ro = (r & 3)*512 + (r >> 2);
        g_WhhF[i] = __float2half(fWhh[(size_t)ro*HID + c]);
        g_WhhG[i] = __float2half(gWhh[(size_t)ro*HID + c]);
    }
    if (i < G4) {
        int o = (i & 3)*512 + (i >> 2);
        g_bcF[i] = fbi[o] + fbh[o];
        g_bcG[i] = gbi[o] + gbh[o];
    }
    if (i < HID*HID) {
        g_W0F[i] = __float2half(fW0[i]); g_W1F[i] = __float2half(fW1[i]);
        g_W0G[i] = __float2half(gW0[i]); g_W1G[i] = __float2half(gW1[i]);
    }
    if (i < BDIM*HID) {
        g_hF0[i] = __float2half(0.f); g_hG0[i] = __float2half(0.f);
        g_cF[i] = 0.f; g_cG[i] = 0.f;
    }
}

// ---------------- SDE paths + sum_inc + payoff ----------------------------
__global__ void k_paths(const float* __restrict__ ts, const float* __restrict__ x0,
                        const float* __restrict__ noise) {
    int gid = blockIdx.x*blockDim.x + threadIdx.x;
    if (gid >= BDIM*DDIM) return;
    int b = gid >> 3, k = gid & 7;
    float x = x0[b*8 + k];
    g_x[(size_t)(b*101)*8 + k] = x;
    float si = 0.f;
    float bk = x;
    #pragma unroll
    for (int s = 1; s < 8; s <<= 1) bk += __shfl_xor_sync(0xffffffffu, bk, s);
    bk *= 0.125f;
    float bmax = bk, blast = bk;
    for (int t = 0; t < NSTEPS; t++) {
        float h  = ts[t+1] - ts[t];
        float dw = noise[((size_t)b*NSTEPS + t)*8 + k] * sqrtf(h);
        x = x + 0.05f*x*h + 0.2f*x*dw;
        g_x[(size_t)(b*101 + t + 1)*8 + k] = x;
        si += dw;
        if ((t % LAGV) == (LAGV-1)) {
            g_suminc[(size_t)(b*WWIN + t/LAGV)*8 + k] = si;
            si = 0.f;
        }
        float bb = x;
        #pragma unroll
        for (int s = 1; s < 8; s <<= 1) bb += __shfl_xor_sync(0xffffffffu, bb, s);
        bb *= 0.125f;
        bmax = fmaxf(bmax, bb);
        blast = bb;
    }
    g_suminc[(size_t)(b*WWIN + 10)*8 + k] = 0.f;
    if (k == 0) g_payoff[b] = bmax - blast;
}

// ---------------- lead-lag signature (depth 3, c=16) ----------------------
__global__ void __launch_bounds__(256) k_sig(const float* __restrict__ ts) {
    __shared__ float S1[16];
    __shared__ float S2[256];
    __shared__ float S3[4096];
    __shared__ float dl[10][8];
    int n = blockIdx.x;
    int b = n / WWIN, w = n - b*WWIN;
    int tid = threadIdx.x;

    if (tid < 80) {
        int i = tid >> 3, k = tid & 7;
        float v;
        if (w == 0) {
            v = (i == 0) ? g_x[(size_t)(b*101)*8 + k] : 0.f;
        } else {
            int base = (w-1)*LAGV + i;
            v = g_x[(size_t)(b*101 + base + 1)*8 + k] - g_x[(size_t)(b*101 + base)*8 + k];
        }
        dl[i][k] = v;
    }
    for (int j = tid; j < 4096; j += 256) S3[j] = 0.f;
    S2[tid] = 0.f;
    if (tid < 16) S1[tid] = 0.f;
    __syncthreads();

    int ni = (w == 0) ? 1 : 10;
    int a = tid >> 4, bbx = tid & 15;
    for (int i = 0; i < ni; i++) {
        #pragma unroll
        for (int ph = 0; ph < 2; ph++) {
            int o = ph ? 0 : 8;
            float s2ab = S2[tid];
            float s1a  = S1[a];
            float db = (bbx >= o && bbx < o+8) ? dl[i][bbx - o] : 0.f;
            float da = (a   >= o && a   < o+8) ? dl[i][a   - o] : 0.f;
            float coef = s2ab + db*(0.5f*s1a + (1.f/6.f)*da);
            float* s3p = &S3[(tid << 4) + o];
            #pragma unroll
            for (int c = 0; c < 8; c++) s3p[c] += coef * dl[i][c];
            __syncthreads();
            if (tid < 128) {
                int aa = tid >> 3, bi = tid & 7;
                float daa = (aa >= o && aa < o+8) ? dl[i][aa - o] : 0.f;
                S2[aa*16 + o + bi] += (S1[aa] + 0.5f*daa) * dl[i][bi];
            }
            __syncthreads();
            if (tid < 8) S1[o + tid] += dl[i][tid];
            __syncthreads();
        }
    }

    float tc = ts[w * LAGV];
    __half* row = &g_txp[(size_t)n * KPAD];
    for (int j = tid; j < KPAD; j += 256) {
        float v;
        if      (j == 0)   v = tc;
        else if (j < 17)   v = S1[j - 1];
        else if (j < 273)  v = S2[j - 17];
        else if (j < KIN)  v = S3[j - 273];
        else               v = 0.f;
        row[j] = __float2half(v);
    }
}

// ---------------- merged skinny output heads (Y + Z, one launch) -----------
__global__ void k_outYZ(const __half* __restrict__ bufY, const float* __restrict__ W2y,
                        const float* __restrict__ b2y,
                        const __half* __restrict__ bufZ, const float* __restrict__ W2z,
                        const float* __restrict__ b2z) {
    int n = blockIdx.x;
    int wrp = threadIdx.x >> 5, lane = threadIdx.x & 31;
    if (wrp < 8) {
        const __half* row = bufZ + (size_t)n*HID;
        const float* wr = W2z + (size_t)wrp*HID;
        float s = 0.f;
        #pragma unroll
        for (int k = lane; k < HID; k += 32) s += __half2float(row[k])*wr[k];
        #pragma unroll
        for (int o = 16; o; o >>= 1) s += __shfl_xor_sync(0xffffffffu, s, o);
        if (lane == 0) g_Z[n*DDIM + wrp] = s + b2z[wrp];
    } else {
        const __half* row = bufY + (size_t)n*HID;
        float s = 0.f;
        #pragma unroll
        for (int k = lane; k < HID; k += 32) s += __half2float(row[k])*W2y[k];
        #pragma unroll
        for (int o = 16; o; o >>= 1) s += __shfl_xor_sync(0xffffffffu, s, o);
        if (lane == 0) g_Y[n] = s + b2y[0];
    }
}

// ---------------- loss + output assembly (deterministic, one block) ------
__global__ void k_loss(const float* __restrict__ ts, float* __restrict__ out) {
    __shared__ float red[1024];
    int b = threadIdx.x;
    float acc = 0.f;
    #pragma unroll 1
    for (int w = 0; w < WWIN; w++) {
        int n = b*WWIN + w;
        float y = g_Y[n];
        float pr = y;
        #pragma unroll
        for (int k = 0; k < DDIM; k++)
            pr += g_Z[n*DDIM + k]*g_suminc[(size_t)n*DDIM + k];
        float tg;
        if (w < WWIN-1) {
            float disc = expf(-0.05f*(ts[w + LAGV] - ts[w*LAGV]));
            tg = disc * g_Y[n + 1];
        } else {
            tg = g_payoff[b];
        }
        float df = pr - tg;
        acc += df*df;
        out[1 + n] = y;
    }
    out[1 + NT + b] = g_payoff[b];
    red[b] = acc;
    __syncthreads();
    for (int s = 512; s > 0; s >>= 1) {
        if (b < s) red[b] += red[b + s];
        __syncthreads();
    }
    if (b == 0) out[0] = red[0] * (1.f/(float)BDIM);
}

// ---------------- host ----------------------------------------------------
extern "C" void kernel_launch(void* const* d_in, const int* in_sizes, int n_in,
                              void* d_out, int out_size) {
    const float* ts    = (const float*)d_in[0];
    const float* x0    = (const float*)d_in[1];
    const float* noise = (const float*)d_in[2];
    const float* fWih = (const float*)d_in[4];
    const float* fWhh = (const float*)d_in[5];
    const float* fbih = (const float*)d_in[6];
    const float* fbhh = (const float*)d_in[7];
    const float* fW0  = (const float*)d_in[8];
    const float* fb0  = (const float*)d_in[9];
    const float* fW1  = (const float*)d_in[10];
    const float* fb1  = (const float*)d_in[11];
    const float* fW2  = (const float*)d_in[12];
    const float* fb2  = (const float*)d_in[13];
    const float* gWih = (const float*)d_in[14];
    const float* gWhh = (const float*)d_in[15];
    const float* gbih = (const float*)d_in[16];
    const float* gbhh = (const float*)d_in[17];
    const float* gW0  = (const float*)d_in[18];
    const float* gb0  = (const float*)d_in[19];
    const float* gW1  = (const float*)d_in[20];
    const float* gb1  = (const float*)d_in[21];
    const float* gW2  = (const float*)d_in[22];
    const float* gb2  = (const float*)d_in[23];
    float* out = (float*)d_out;

    cudaFuncSetAttribute(tc_proj2, cudaFuncAttributeMaxDynamicSharedMemorySize, TG_SMEM64);
    cudaFuncSetAttribute(tc_ffn2,  cudaFuncAttributeMaxDynamicSharedMemorySize, TG_SMEM32);
    cudaFuncSetAttribute(tc_cell,  cudaFuncAttributeMaxDynamicSharedMemorySize, TG_SMEM32);

    __half *p_txp,*p_WihF,*p_WihG,*p_hsF,*p_hsG;
    __half *p_bufA,*p_bufB,*p_bufA2,*p_bufB2;
    __half *p_W0F,*p_W1F,*p_W0G,*p_W1G;
    __half *p_hF0,*p_hF1,*p_hG0,*p_hG1;
    float *p_preF,*p_preG;
    cudaGetSymbolAddress((void**)&p_txp,  g_txp);
    cudaGetSymbolAddress((void**)&p_WihF, g_WihF);
    cudaGetSymbolAddress((void**)&p_WihG, g_WihG);
    cudaGetSymbolAddress((void**)&p_preF, g_preF);
    cudaGetSymbolAddress((void**)&p_preG, g_preG);
    cudaGetSymbolAddress((void**)&p_hsF,  g_hsF);
    cudaGetSymbolAddress((void**)&p_hsG,  g_hsG);
    cudaGetSymbolAddress((void**)&p_bufA, g_bufA);
    cudaGetSymbolAddress((void**)&p_bufB, g_bufB);
    cudaGetSymbolAddress((void**)&p_bufA2, g_bufA2);
    cudaGetSymbolAddress((void**)&p_bufB2, g_bufB2);
    cudaGetSymbolAddress((void**)&p_W0F,  g_W0F);
    cudaGetSymbolAddress((void**)&p_W1F,  g_W1F);
    cudaGetSymbolAddress((void**)&p_W0G,  g_W0G);
    cudaGetSymbolAddress((void**)&p_W1G,  g_W1G);
    cudaGetSymbolAddress((void**)&p_hF0,  g_hF0);
    cudaGetSymbolAddress((void**)&p_hF1,  g_hF1);
    cudaGetSymbolAddress((void**)&p_hG0,  g_hG0);
    cudaGetSymbolAddress((void**)&p_hG1,  g_hG1);

    k_prep <<<(G4*KPAD + 255)/256, 256>>>(fWih, gWih, fWhh, gWhh,
                                          fbih, fbhh, gbih, gbhh,
                                          fW0, fW1, gW0, gW1);
    k_paths<<<(BDIM*DDIM + 255)/256, 256>>>(ts, x0, noise);
    k_sig  <<<NT, 256>>>(ts);

    // input projections: BK=64 (long K), both nets fused
    dim3 g1(G4/256, NT/128, 2);
    tc_proj2<<<g1, 512, TG_SMEM64>>>(p_txp, p_WihF, p_preF,
                                     p_txp, p_WihG, p_preG,
                                     KPAD, KPAD, G4, KPAD);

    // recurrence: BK=32 (short K), 11 per-step launches, 128-M tile,
    // fused LSTM cell (fast sigmoid/tanh), h ping-ponged (race fix — keep!).
    __half* hF[2] = { p_hF0, p_hF1 };
    __half* hG[2] = { p_hG0, p_hG1 };
    dim3 g2(G4/256, BDIM/128, 2);
    for (int t = 0; t < WWIN; t++)
        tc_cell<<<g2, 512, TG_SMEM32>>>(hF[t & 1], hF[(t + 1) & 1],
                                        hG[t & 1], hG[(t + 1) & 1], t);

    // FFN heads: BK=32 (short K), both nets fused per layer
    dim3 g3(HID/256, NT/128, 2);
    tc_ffn2<<<g3, 512, TG_SMEM32>>>(p_hsF,  p_W0F, p_bufA,  fb0,
                                    p_hsG,  p_W0G, p_bufA2, gb0,
                                    HID, HID, HID, HID, 1);
    tc_ffn2<<<g3, 512, TG_SMEM32>>>(p_bufA,  p_W1F, p_bufB,  fb1,
                                    p_bufA2, p_W1G, p_bufB2, gb1,
                                    HID, HID, HID, HID, 1);
    k_outYZ<<<NT, 288>>>(p_bufB, fW2, fb2, p_bufB2, gW2, gb2);

    // loss + output: [loss(1), Y(11264), payoff(1024)]
    k_loss<<<1, 1024>>>(ts, out);
}

// round 17
// speedup vs baseline: 1.0404x; 1.0191x over previous
#include <cuda_runtime.h>
#include <cuda_fp16.h>
#include <math.h>
#include <stdint.h>

// Shapes (fixed by the problem)
#define BDIM 1024
#define DDIM 8
#define NSTEPS 100
#define LAGV 10
#define WWIN 11
#define NT (BDIM*WWIN)        // 11264 rows (b*11+w)
#define KIN 4369
#define KPAD 4416             // /64 halves
#define HID 512
#define G4 2048               // 4*HID gate width

// ---------------- scratch (device globals; no allocation allowed) ----------
__device__ __align__(16) float g_x[BDIM*(NSTEPS+1)*DDIM];
__device__ __align__(16) float g_suminc[BDIM*WWIN*DDIM];
__device__ __align__(16) float g_payoff[BDIM];
__device__ __align__(16) __half g_txp[(size_t)NT*KPAD];       // fp16 signature rows
__device__ __align__(16) __half g_WihF[(size_t)G4*KPAD];      // gate-permuted fp16
__device__ __align__(16) __half g_WihG[(size_t)G4*KPAD];
__device__ __align__(16) __half g_WhhF[(size_t)G4*HID];
__device__ __align__(16) __half g_WhhG[(size_t)G4*HID];
__device__ __align__(16) float  g_bcF[G4], g_bcG[G4];         // combined bias (fp32)
__device__ __align__(16) __half g_W0F[HID*HID], g_W1F[HID*HID];
__device__ __align__(16) __half g_W0G[HID*HID], g_W1G[HID*HID];
__device__ __align__(16) float  g_preF[(size_t)NT*G4];        // fp32 pre-activations
__device__ __align__(16) float  g_preG[(size_t)NT*G4];
__device__ __align__(16) __half g_hF0[BDIM*HID], g_hF1[BDIM*HID];   // ping-pong h
__device__ __align__(16) __half g_hG0[BDIM*HID], g_hG1[BDIM*HID];
__device__ __align__(16) float  g_cF[BDIM*HID], g_cG[BDIM*HID];
__device__ __align__(16) __half g_hsF[(size_t)NT*HID], g_hsG[(size_t)NT*HID];
__device__ __align__(16) __half g_bufA[(size_t)NT*HID],  g_bufB[(size_t)NT*HID];
__device__ __align__(16) __half g_bufA2[(size_t)NT*HID], g_bufB2[(size_t)NT*HID];
__device__ float g_Y[NT];
__device__ float g_Z[NT*DDIM];

// ---------------- helpers -------------------------------------------------
__device__ __forceinline__ void cpasync16(uint32_t dst, const void* src) {
    asm volatile("cp.async.cg.shared.global [%0], [%1], 16;" :: "r"(dst), "l"(src));
}
__device__ __forceinline__ void cpcommit() {
    asm volatile("cp.async.commit_group;");
}
template<int NPend> __device__ __forceinline__ void cpwait() {
    asm volatile("cp.async.wait_group %0;" :: "n"(NPend));
}
__device__ __forceinline__ void ldm4(uint32_t addr, uint32_t& r0, uint32_t& r1,
                                     uint32_t& r2, uint32_t& r3) {
    asm volatile("ldmatrix.sync.aligned.m8n8.x4.shared.b16 {%0,%1,%2,%3}, [%4];"
                 : "=r"(r0), "=r"(r1), "=r"(r2), "=r"(r3) : "r"(addr));
}
__device__ __forceinline__ void mma16(float& c0, float& c1, float& c2, float& c3,
                                      uint32_t a0, uint32_t a1, uint32_t a2, uint32_t a3,
                                      uint32_t b0, uint32_t b1) {
    asm volatile(
        "mma.sync.aligned.m16n8k16.row.col.f32.f16.f16.f32 "
        "{%0,%1,%2,%3}, {%4,%5,%6,%7}, {%8,%9}, {%0,%1,%2,%3};"
        : "+f"(c0), "+f"(c1), "+f"(c2), "+f"(c3)
        : "r"(a0), "r"(a1), "r"(a2), "r"(a3), "r"(b0), "r"(b1));
}
// fast sigmoid / tanh via MUFU ex2 + fast reciprocal (rel err ~1e-6)
__device__ __forceinline__ float fsigm(float x) {
    return __fdividef(1.f, 1.f + __expf(-x));
}
__device__ __forceinline__ float ftanh(float x) {
    float e = __expf(-2.f * x);
    return __fdividef(1.f - e, 1.f + e);
}

// ---------------- FP16 GEMM core: C[m,n] = sum_k A[m,k]*B[n,k] ------------
// CTA tile 128(M)x256(N), 512 threads, 16 warps (warp tile 32x64).
// BK=64 everywhere (halves barrier count vs BK=32); stage depth tuned:
//   NST=4 (221KB) — long-K projections (prologue amortized over 69 ktiles)
//   NST=3 (166KB) — short-K recurrence/FFN (prologue = 25% of 8 ktiles,
//                    same fraction as the old BK=32/5-stage, half the barriers)
// Single __syncthreads per ktile; next stage issued AFTER the MMA block
// (round-15 finding: issuing before MMAs bloats live regs and stalls HMMA).
// MODE 0 = plain epilogue (OUTH half/float), MODE 1 = fused LSTM cell
// (ping-pong h: reads hin, writes hout — NEVER in place; round-7 race fix).
#define PITCHH 72u                    // halves per smem row (144B, conflict-free)
#define STBB   ((128u+256u)*PITCHH*2u) // 55296 bytes/stage
#define TG_SMEM_P (4*(int)STBB)       // 221184 (projections)
#define TG_SMEM_S (3*(int)STBB)       // 165888 (short-K)

template<int MODE, int OUTH, int NST>
__device__ __forceinline__ void tc_body(
    const __half* __restrict__ A, int lda,
    const __half* __restrict__ B, int ldb,
    void* __restrict__ C, int ldc, int K,
    const float* __restrict__ bias, int relu,
    const float* __restrict__ pre,     // MODE 1
    float* __restrict__ cst, __half* __restrict__ hout,
    __half* __restrict__ hs, int t,
    int bm, int bn)
{
    constexpr uint32_t PB  = PITCHH * 2u;           // 144 bytes/row
    constexpr uint32_t AHL = 128u * PITCHH;

    extern __shared__ float sm[];
    uint32_t smu = (uint32_t)__cvta_generic_to_shared(sm);
    int tid = threadIdx.x, warp = tid >> 5, lane = tid & 31;
    int wm = (warp >> 2) * 32;       // 4 M-slices of 32
    int wn = (warp & 3) * 64;        // 4 N-slices of 64
    int gid = lane >> 2, tig = lane & 3;

    // ldmatrix per-lane selectors (b16, 16B rows = 8 halves)
    int a_row = lane & 15;
    uint32_t akb = (uint32_t)(lane >> 4) * 16u;      // k-half offset bytes
    int b_row = ((lane & 16) >> 1) + (lane & 7);
    uint32_t bkb = (lane & 8) ? 16u : 0u;

    float acc[2][8][4];
    #pragma unroll
    for (int i = 0; i < 2; i++)
        #pragma unroll
        for (int j = 0; j < 8; j++)
            #pragma unroll
            for (int q = 0; q < 4; q++) acc[i][j][q] = 0.f;

    int nk = K >> 6;                 // BK = 64

    // stage issue: A 128x8 chunks (2/thread), B 256x8 chunks (4/thread)
    auto issue = [&](int kt, int slot) {
        uint32_t base = smu + (uint32_t)slot * STBB;
        int k0 = kt * 64;
        #pragma unroll
        for (int j = 0; j < 2; j++) {
            int idx = tid + j*512;
            int row = idx >> 3, c = idx & 7;
            cpasync16(base + (uint32_t)row*PB + (uint32_t)c*16u,
                      A + (size_t)(bm + row)*lda + k0 + c*8);
        }
        uint32_t bbase = base + AHL*2u;
        #pragma unroll
        for (int j = 0; j < 4; j++) {
            int idx = tid + j*512;
            int row = idx >> 3, c = idx & 7;
            cpasync16(bbase + (uint32_t)row*PB + (uint32_t)c*16u,
                      B + (size_t)(bn + row)*ldb + k0 + c*8);
        }
    };

    #pragma unroll
    for (int p = 0; p < NST-1; p++) { issue(p, p); cpcommit(); }

    for (int kt = 0; kt < nk; kt++) {
        cpwait<NST-2>();                  // stage kt complete
        __syncthreads();

        uint32_t aB = smu + (uint32_t)(kt % NST) * STBB;
        uint32_t bB = aB + AHL*2u;
        #pragma unroll
        for (int s = 0; s < 4; s++) {     // four k16 steps per 64-K tile
            uint32_t af[2][4], bf[4][4];
            #pragma unroll
            for (int mf = 0; mf < 2; mf++)
                ldm4(aB + (uint32_t)(wm + mf*16 + a_row)*PB + (uint32_t)s*32u + akb,
                     af[mf][0], af[mf][1], af[mf][2], af[mf][3]);
            #pragma unroll
            for (int np = 0; np < 4; np++)
                ldm4(bB + (uint32_t)(wn + np*16 + b_row)*PB + (uint32_t)s*32u + bkb,
                     bf[np][0], bf[np][1], bf[np][2], bf[np][3]);
            #pragma unroll
            for (int mf = 0; mf < 2; mf++)
                #pragma unroll
                for (int nf = 0; nf < 8; nf++) {
                    int np = nf >> 1, hh = (nf & 1) * 2;
                    mma16(acc[mf][nf][0], acc[mf][nf][1], acc[mf][nf][2], acc[mf][nf][3],
                          af[mf][0], af[mf][1], af[mf][2], af[mf][3],
                          bf[np][hh], bf[np][hh+1]);
                }
        }
        // issue into slot (kt+NST-1)%NST == (kt-1)%NST: free after barrier
        if (kt + NST-1 < nk) issue(kt + NST-1, (kt + NST-1) % NST);
        cpcommit();                       // uniform group count
    }

    if (MODE == 0) {
        #pragma unroll
        for (int mf = 0; mf < 2; mf++) {
            #pragma unroll
            for (int nf = 0; nf < 8; nf++) {
                int r0 = bm + wm + mf*16 + gid;
                int cc = bn + wn + nf*8 + 2*tig;
                float b0v = bias ? bias[cc]   : 0.f;
                float b1v = bias ? bias[cc+1] : 0.f;
                float v0 = acc[mf][nf][0] + b0v;
                float v1 = acc[mf][nf][1] + b1v;
                float v2 = acc[mf][nf][2] + b0v;
                float v3 = acc[mf][nf][3] + b1v;
                if (relu) { v0=fmaxf(v0,0.f); v1=fmaxf(v1,0.f);
                            v2=fmaxf(v2,0.f); v3=fmaxf(v3,0.f); }
                if (OUTH) {
                    __half* Ch = (__half*)C;
                    *(__half2*)&Ch[(size_t)r0*ldc + cc]     = __floats2half2_rn(v0, v1);
                    *(__half2*)&Ch[(size_t)(r0+8)*ldc + cc] = __floats2half2_rn(v2, v3);
                } else {
                    float* Cf = (float*)C;
                    *(float2*)&Cf[(size_t)r0*ldc + cc]     = make_float2(v0, v1);
                    *(float2*)&Cf[(size_t)(r0+8)*ldc + cc] = make_float2(v2, v3);
                }
            }
        }
    } else {
        // fused LSTM cell: cols are gate-interleaved (4u+{i,f,g,o})
        #pragma unroll
        for (int mf = 0; mf < 2; mf++) {
            #pragma unroll
            for (int nf = 0; nf < 8; nf++) {
                int r0 = bm + wm + mf*16 + gid;          // batch index (even-lane row)
                int cc = bn + wn + nf*8 + 2*tig;
                size_t n0 = ((size_t)r0*WWIN + t)*G4;
                size_t n1 = ((size_t)(r0+8)*WWIN + t)*G4;
                float bc0 = bias[cc], bc1 = bias[cc+1];
                float v0 = acc[mf][nf][0] + pre[n0 + cc]     + bc0;
                float v1 = acc[mf][nf][1] + pre[n0 + cc + 1] + bc1;
                float v2 = acc[mf][nf][2] + pre[n1 + cc]     + bc0;
                float v3 = acc[mf][nf][3] + pre[n1 + cc + 1] + bc1;
                int odd = tig & 1;
                float s0 = odd ? v0 : v2;
                float s1 = odd ? v1 : v3;
                float x0 = __shfl_xor_sync(0xffffffffu, s0, 1);
                float x1 = __shfl_xor_sync(0xffffffffu, s1, 1);
                float gi = odd ? x0 : v0;
                float gf = odd ? x1 : v1;
                float gg = odd ? v2 : x0;
                float go = odd ? v3 : x1;
                int brow = r0 + (odd ? 8 : 0);
                int u = ((bn + wn + nf*8) >> 2) + (tig >> 1);
                int idx = brow*HID + u;
                float cv = cst[idx];
                cv = fsigm(gf)*cv + fsigm(gi)*ftanh(gg);
                float hv = fsigm(go)*ftanh(cv);
                cst[idx] = cv;
                __half hvh = __float2half(hv);
                hout[idx] = hvh;
                hs[((size_t)brow*WWIN + t)*HID + u] = hvh;
            }
        }
    }
}

// projections: BK=64, 4 stages, dual-net via z
__global__ void __launch_bounds__(512, 1) tc_proj2(
    const __half* __restrict__ A0, const __half* __restrict__ B0,
    float* __restrict__ C0,
    const __half* __restrict__ A1, const __half* __restrict__ B1,
    float* __restrict__ C1,
    int lda, int ldb, int ldc, int K)
{
    int z = blockIdx.z;
    tc_body<0,0,4>(z ? A1 : A0, lda, z ? B1 : B0, ldb,
                   z ? (void*)C1 : (void*)C0, ldc, K, nullptr, 0,
                   nullptr, nullptr, nullptr, nullptr, 0,
                   blockIdx.y*128, blockIdx.x*256);
}

// FFN: BK=64, 3 stages, half output, dual-net via z
__global__ void __launch_bounds__(512, 1) tc_ffn2(
    const __half* __restrict__ A0, const __half* __restrict__ B0,
    __half* __restrict__ C0, const float* __restrict__ bias0,
    const __half* __restrict__ A1, const __half* __restrict__ B1,
    __half* __restrict__ C1, const float* __restrict__ bias1,
    int lda, int ldb, int ldc, int K, int relu)
{
    int z = blockIdx.z;
    tc_body<0,1,3>(z ? A1 : A0, lda, z ? B1 : B0, ldb,
                   z ? (void*)C1 : (void*)C0, ldc, K,
                   z ? bias1 : bias0, relu,
                   nullptr, nullptr, nullptr, nullptr, 0,
                   blockIdx.y*128, blockIdx.x*256);
}

// recurrence: BK=64, 3 stages, fused LSTM cell, ping-pong h (never in place)
__global__ void __launch_bounds__(512, 1) tc_cell(
    const __half* __restrict__ hinF, __half* __restrict__ houtF,
    const __half* __restrict__ hinG, __half* __restrict__ houtG, int t)
{
    int z = blockIdx.z;
    tc_body<1,0,3>(z ? hinG : hinF, HID, z ? g_WhhG : g_WhhF, HID,
                   nullptr, 0, HID, z ? g_bcG : g_bcF, 0,
                   z ? g_preG : g_preF,
                   z ? g_cG : g_cF, z ? houtG : houtF, z ? g_hsG : g_hsF, t,
                   blockIdx.y*128, blockIdx.x*256);
}

// ---------------- merged preprocessing (one launch) ------------------------
// permuted row p <- orig row (p&3)*512 + (p>>2)
__global__ void k_prep(const float* __restrict__ fWih, const float* __restrict__ gWih,
                       const float* __restrict__ fWhh, const float* __restrict__ gWhh,
                       const float* __restrict__ fbi,  const float* __restrict__ fbh,
                       const float* __restrict__ gbi,  const float* __restrict__ gbh,
                       const float* __restrict__ fW0,  const float* __restrict__ fW1,
                       const float* __restrict__ gW0,  const float* __restrict__ gW1) {
    int i = blockIdx.x*blockDim.x + threadIdx.x;
    if (i < G4*KPAD) {
        int r = i / KPAD, c = i - r*KPAD;
        int ro = (r & 3)*512 + (r >> 2);
        float vf = 0.f, vg = 0.f;
        if (c < KIN) { vf = fWih[(size_t)ro*KIN + c]; vg = gWih[(size_t)ro*KIN + c]; }
        g_WihF[i] = __float2half(vf); g_WihG[i] = __float2half(vg);
    }
    if (i < G4*HID) {
        int r = i / HID, c = i - r*HID;
        int ro = (r & 3)*512 + (r >> 2);
        g_WhhF[i] = __float2half(fWhh[(size_t)ro*HID + c]);
        g_WhhG[i] = __float2half(gWhh[(size_t)ro*HID + c]);
    }
    if (i < G4) {
        int o = (i & 3)*512 + (i >> 2);
        g_bcF[i] = fbi[o] + fbh[o];
        g_bcG[i] = gbi[o] + gbh[o];
    }
    if (i < HID*HID) {
        g_W0F[i] = __float2half(fW0[i]); g_W1F[i] = __float2half(fW1[i]);
        g_W0G[i] = __float2half(gW0[i]); g_W1G[i] = __float2half(gW1[i]);
    }
    if (i < BDIM*HID) {
        g_hF0[i] = __float2half(0.f); g_hG0[i] = __float2half(0.f);
        g_cF[i] = 0.f; g_cG[i] = 0.f;
    }
}

// ---------------- SDE paths + sum_inc + payoff ----------------------------
__global__ void k_paths(const float* __restrict__ ts, const float* __restrict__ x0,
                        const float* __restrict__ noise) {
    int gid = blockIdx.x*blockDim.x + threadIdx.x;
    if (gid >= BDIM*DDIM) return;
    int b = gid >> 3, k = gid & 7;
    float x = x0[b*8 + k];
    g_x[(size_t)(b*101)*8 + k] = x;
    float si = 0.f;
    float bk = x;
    #pragma unroll
    for (int s = 1; s < 8; s <<= 1) bk += __shfl_xor_sync(0xffffffffu, bk, s);
    bk *= 0.125f;
    float bmax = bk, blast = bk;
    for (int t = 0; t < NSTEPS; t++) {
        float h  = ts[t+1] - ts[t];
        float dw = noise[((size_t)b*NSTEPS + t)*8 + k] * sqrtf(h);
        x = x + 0.05f*x*h + 0.2f*x*dw;
        g_x[(size_t)(b*101 + t + 1)*8 + k] = x;
        si += dw;
        if ((t % LAGV) == (LAGV-1)) {
            g_suminc[(size_t)(b*WWIN + t/LAGV)*8 + k] = si;
            si = 0.f;
        }
        float bb = x;
        #pragma unroll
        for (int s = 1; s < 8; s <<= 1) bb += __shfl_xor_sync(0xffffffffu, bb, s);
        bb *= 0.125f;
        bmax = fmaxf(bmax, bb);
        blast = bb;
    }
    g_suminc[(size_t)(b*WWIN + 10)*8 + k] = 0.f;
    if (k == 0) g_payoff[b] = bmax - blast;
}

// ---------------- lead-lag signature (depth 3, c=16) ----------------------
__global__ void __launch_bounds__(256) k_sig(const float* __restrict__ ts) {
    __shared__ float S1[16];
    __shared__ float S2[256];
    __shared__ float S3[4096];
    __shared__ float dl[10][8];
    int n = blockIdx.x;
    int b = n / WWIN, w = n - b*WWIN;
    int tid = threadIdx.x;

    if (tid < 80) {
        int i = tid >> 3, k = tid & 7;
        float v;
        if (w == 0) {
            v = (i == 0) ? g_x[(size_t)(b*101)*8 + k] : 0.f;
        } else {
            int base = (w-1)*LAGV + i;
            v = g_x[(size_t)(b*101 + base + 1)*8 + k] - g_x[(size_t)(b*101 + base)*8 + k];
        }
        dl[i][k] = v;
    }
    for (int j = tid; j < 4096; j += 256) S3[j] = 0.f;
    S2[tid] = 0.f;
    if (tid < 16) S1[tid] = 0.f;
    __syncthreads();

    int ni = (w == 0) ? 1 : 10;
    int a = tid >> 4, bbx = tid & 15;
    for (int i = 0; i < ni; i++) {
        #pragma unroll
        for (int ph = 0; ph < 2; ph++) {
            int o = ph ? 0 : 8;
            float s2ab = S2[tid];
            float s1a  = S1[a];
            float db = (bbx >= o && bbx < o+8) ? dl[i][bbx - o] : 0.f;
            float da = (a   >= o && a   < o+8) ? dl[i][a   - o] : 0.f;
            float coef = s2ab + db*(0.5f*s1a + (1.f/6.f)*da);
            float* s3p = &S3[(tid << 4) + o];
            #pragma unroll
            for (int c = 0; c < 8; c++) s3p[c] += coef * dl[i][c];
            __syncthreads();
            if (tid < 128) {
                int aa = tid >> 3, bi = tid & 7;
                float daa = (aa >= o && aa < o+8) ? dl[i][aa - o] : 0.f;
                S2[aa*16 + o + bi] += (S1[aa] + 0.5f*daa) * dl[i][bi];
            }
            __syncthreads();
            if (tid < 8) S1[o + tid] += dl[i][tid];
            __syncthreads();
        }
    }

    float tc = ts[w * LAGV];
    __half* row = &g_txp[(size_t)n * KPAD];
    for (int j = tid; j < KPAD; j += 256) {
        float v;
        if      (j == 0)   v = tc;
        else if (j < 17)   v = S1[j - 1];
        else if (j < 273)  v = S2[j - 17];
        else if (j < KIN)  v = S3[j - 273];
        else               v = 0.f;
        row[j] = __float2half(v);
    }
}

// ---------------- merged skinny output heads (Y + Z, one launch) -----------
__global__ void k_outYZ(const __half* __restrict__ bufY, const float* __restrict__ W2y,
                        const float* __restrict__ b2y,
                        const __half* __restrict__ bufZ, const float* __restrict__ W2z,
                        const float* __restrict__ b2z) {
    int n = blockIdx.x;
    int wrp = threadIdx.x >> 5, lane = threadIdx.x & 31;
    if (wrp < 8) {
        const __half* row = bufZ + (size_t)n*HID;
        const float* wr = W2z + (size_t)wrp*HID;
        float s = 0.f;
        #pragma unroll
        for (int k = lane; k < HID; k += 32) s += __half2float(row[k])*wr[k];
        #pragma unroll
        for (int o = 16; o; o >>= 1) s += __shfl_xor_sync(0xffffffffu, s, o);
        if (lane == 0) g_Z[n*DDIM + wrp] = s + b2z[wrp];
    } else {
        const __half* row = bufY + (size_t)n*HID;
        float s = 0.f;
        #pragma unroll
        for (int k = lane; k < HID; k += 32) s += __half2float(row[k])*W2y[k];
        #pragma unroll
        for (int o = 16; o; o >>= 1) s += __shfl_xor_sync(0xffffffffu, s, o);
        if (lane == 0) g_Y[n] = s + b2y[0];
    }
}

// ---------------- loss + output assembly (deterministic, one block) ------
__global__ void k_loss(const float* __restrict__ ts, float* __restrict__ out) {
    __shared__ float red[1024];
    int b = threadIdx.x;
    float acc = 0.f;
    #pragma unroll 1
    for (int w = 0; w < WWIN; w++) {
        int n = b*WWIN + w;
        float y = g_Y[n];
        float pr = y;
        #pragma unroll
        for (int k = 0; k < DDIM; k++)
            pr += g_Z[n*DDIM + k]*g_suminc[(size_t)n*DDIM + k];
        float tg;
        if (w < WWIN-1) {
            float disc = expf(-0.05f*(ts[w + LAGV] - ts[w*LAGV]));
            tg = disc * g_Y[n + 1];
        } else {
            tg = g_payoff[b];
        }
        float df = pr - tg;
        acc += df*df;
        out[1 + n] = y;
    }
    out[1 + NT + b] = g_payoff[b];
    red[b] = acc;
    __syncthreads();
    for (int s = 512; s > 0; s >>= 1) {
        if (b < s) red[b] += red[b + s];
        __syncthreads();
    }
    if (b == 0) out[0] = red[0] * (1.f/(float)BDIM);
}

// ---------------- host ----------------------------------------------------
extern "C" void kernel_launch(void* const* d_in, const int* in_sizes, int n_in,
                              void* d_out, int out_size) {
    const float* ts    = (const float*)d_in[0];
    const float* x0    = (const float*)d_in[1];
    const float* noise = (const float*)d_in[2];
    const float* fWih = (const float*)d_in[4];
    const float* fWhh = (const float*)d_in[5];
    const float* fbih = (const float*)d_in[6];
    const float* fbhh = (const float*)d_in[7];
    const float* fW0  = (const float*)d_in[8];
    const float* fb0  = (const float*)d_in[9];
    const float* fW1  = (const float*)d_in[10];
    const float* fb1  = (const float*)d_in[11];
    const float* fW2  = (const float*)d_in[12];
    const float* fb2  = (const float*)d_in[13];
    const float* gWih = (const float*)d_in[14];
    const float* gWhh = (const float*)d_in[15];
    const float* gbih = (const float*)d_in[16];
    const float* gbhh = (const float*)d_in[17];
    const float* gW0  = (const float*)d_in[18];
    const float* gb0  = (const float*)d_in[19];
    const float* gW1  = (const float*)d_in[20];
    const float* gb1  = (const float*)d_in[21];
    const float* gW2  = (const float*)d_in[22];
    const float* gb2  = (const float*)d_in[23];
    float* out = (float*)d_out;

    cudaFuncSetAttribute(tc_proj2, cudaFuncAttributeMaxDynamicSharedMemorySize, TG_SMEM_P);
    cudaFuncSetAttribute(tc_ffn2,  cudaFuncAttributeMaxDynamicSharedMemorySize, TG_SMEM_S);
    cudaFuncSetAttribute(tc_cell,  cudaFuncAttributeMaxDynamicSharedMemorySize, TG_SMEM_S);

    __half *p_txp,*p_WihF,*p_WihG,*p_hsF,*p_hsG;
    __half *p_bufA,*p_bufB,*p_bufA2,*p_bufB2;
    __half *p_W0F,*p_W1F,*p_W0G,*p_W1G;
    __half *p_hF0,*p_hF1,*p_hG0,*p_hG1;
    float *p_preF,*p_preG;
    cudaGetSymbolAddress((void**)&p_txp,  g_txp);
    cudaGetSymbolAddress((void**)&p_WihF, g_WihF);
    cudaGetSymbolAddress((void**)&p_WihG, g_WihG);
    cudaGetSymbolAddress((void**)&p_preF, g_preF);
    cudaGetSymbolAddress((void**)&p_preG, g_preG);
    cudaGetSymbolAddress((void**)&p_hsF,  g_hsF);
    cudaGetSymbolAddress((void**)&p_hsG,  g_hsG);
    cudaGetSymbolAddress((void**)&p_bufA, g_bufA);
    cudaGetSymbolAddress((void**)&p_bufB, g_bufB);
    cudaGetSymbolAddress((void**)&p_bufA2, g_bufA2);
    cudaGetSymbolAddress((void**)&p_bufB2, g_bufB2);
    cudaGetSymbolAddress((void**)&p_W0F,  g_W0F);
    cudaGetSymbolAddress((void**)&p_W1F,  g_W1F);
    cudaGetSymbolAddress((void**)&p_W0G,  g_W0G);
    cudaGetSymbolAddress((void**)&p_W1G,  g_W1G);
    cudaGetSymbolAddress((void**)&p_hF0,  g_hF0);
    cudaGetSymbolAddress((void**)&p_hF1,  g_hF1);
    cudaGetSymbolAddress((void**)&p_hG0,  g_hG0);
    cudaGetSymbolAddress((void**)&p_hG1,  g_hG1);

    k_prep <<<(G4*KPAD + 255)/256, 256>>>(fWih, gWih, fWhh, gWhh,
                                          fbih, fbhh, gbih, gbhh,
                                          fW0, fW1, gW0, gW1);
    k_paths<<<(BDIM*DDIM + 255)/256, 256>>>(ts, x0, noise);
    k_sig  <<<NT, 256>>>(ts);

    // input projections: BK=64, 4 stages (long K), both nets fused
    dim3 g1(G4/256, NT/128, 2);
    tc_proj2<<<g1, 512, TG_SMEM_P>>>(p_txp, p_WihF, p_preF,
                                     p_txp, p_WihG, p_preG,
                                     KPAD, KPAD, G4, KPAD);

    // recurrence: BK=64, 3 stages (short K — 25% prologue, half the barriers),
    // 11 per-step launches, 128-M tile, fused LSTM cell (fast sigmoid/tanh),
    // h ping-ponged (round-7 race fix — keep!).
    __half* hF[2] = { p_hF0, p_hF1 };
    __half* hG[2] = { p_hG0, p_hG1 };
    dim3 g2(G4/256, BDIM/128, 2);
    for (int t = 0; t < WWIN; t++)
        tc_cell<<<g2, 512, TG_SMEM_S>>>(hF[t & 1], hF[(t + 1) & 1],
                                        hG[t & 1], hG[(t + 1) & 1], t);

    // FFN heads: BK=64, 3 stages (short K), both nets fused per layer
    dim3 g3(HID/256, NT/128, 2);
    tc_ffn2<<<g3, 512, TG_SMEM_S>>>(p_hsF,  p_W0F, p_bufA,  fb0,
                                    p_hsG,  p_W0G, p_bufA2, gb0,
                                    HID, HID, HID, HID, 1);
    tc_ffn2<<<g3, 512, TG_SMEM_S>>>(p_bufA,  p_W1F, p_bufB,  fb1,
                                    p_bufA2, p_W1G, p_bufB2, gb1,
                                    HID, HID, HID, HID, 1);
    k_outYZ<<<NT, 288>>>(p_bufB, fW2, fb2, p_bufB2, gW2, gb2);

    // loss + output: [loss(1), Y(11264), payoff(1024)]
    k_loss<<<1, 1024>>>(ts, out);
}